// round 8
// baseline (speedup 1.0000x reference)
#include <cuda_runtime.h>
#include <cuda_fp16.h>
#include <cstdint>
#include <math.h>

#define HIDDEN   1024
#define BATCH    512
#define FEAT     1024
#define TSTEPS   100
#define TIME_TOT 103
#define FOURH    4096
#define MTOT     (TSTEPS * BATCH)   // 51200

#define STAGE_B  32768
#define SMEM_SZ  (4 * STAGE_B)      // 131072
#define NTHR     512

// ------------------------------ scratch (device globals, no allocs) ----------
__device__ __align__(16) __half g_WRp[32 * 32 * 8192];         // [W;R] fp16 per-strip (16MB)
__device__ __align__(16) __half g_xp[(size_t)MTOT * 1024];     // permuted x fp16 (100MB)
__device__ __align__(16) __half g_hp[2][BATCH * HIDDEN];       // permuted h fp16 ping-pong
__device__ unsigned g_sync4[4];                                // per-by-group barrier counters

// ------------------------------ asm helpers ----------------------------------
#define CP16(dst, src) \
    asm volatile("cp.async.cg.shared.global [%0], [%1], 16;" :: "r"(dst), "l"(src))
#define CP_COMMIT() asm volatile("cp.async.commit_group;" ::: "memory")
#define CP_WAIT2()  asm volatile("cp.async.wait_group 2;" ::: "memory")

__device__ __forceinline__ uint4 lds128u(uint32_t a) {
    uint4 v;
    asm volatile("ld.shared.v4.b32 {%0,%1,%2,%3}, [%4];"
                 : "=r"(v.x), "=r"(v.y), "=r"(v.z), "=r"(v.w) : "r"(a));
    return v;
}
__device__ __forceinline__ uint2 lds64u(uint32_t a) {
    uint2 v;
    asm volatile("ld.shared.v2.b32 {%0,%1}, [%2];" : "=r"(v.x), "=r"(v.y) : "r"(a));
    return v;
}
__device__ __forceinline__ void mma_f16(float c[4], uint4 a, uint2 b) {
    asm volatile(
        "mma.sync.aligned.m16n8k16.row.col.f32.f16.f16.f32 "
        "{%0,%1,%2,%3}, {%4,%5,%6,%7}, {%8,%9}, {%0,%1,%2,%3};"
        : "+f"(c[0]), "+f"(c[1]), "+f"(c[2]), "+f"(c[3])
        : "r"(a.x), "r"(a.y), "r"(a.z), "r"(a.w), "r"(b.x), "r"(b.y));
}

// fast transcendentals
__device__ __forceinline__ float sigm_f(float z) {
    return __fdividef(1.f, 1.f + __expf(-z));
}
__device__ __forceinline__ float tanh_f(float z) {
    return 1.f - __fdividef(2.f, __expf(2.f * z) + 1.f);
}

// ------------------------------ prep (single launch) --------------------------
#define N1 (32 * 32 * 4096)          // WRp half2 elems
#define N2 (MTOT * 1024 / 16)        // xp 16-float chunks
#define N3 (BATCH * HIDDEN / 2)      // hp[0] zero words

__global__ void prep_all(const float* __restrict__ W, const float* __restrict__ R,
                         const float* __restrict__ x)
{
    int idx = blockIdx.x * blockDim.x + threadIdx.x;
    if (idx < N1) {
        int v   = idx & 3;
        int tig = (idx >> 2) & 3;
        int grp = (idx >> 4) & 7;
        int k16 = (idx >> 7) & 3;
        int mi  = (idx >> 9) & 3;
        int wm  = (idx >> 11) & 1;
        int kt  = (idx >> 12) & 31;
        int cb  = idx >> 17;
        int r8  = v & 1;
        int khi = (v >> 1) * 8;
        int q   = mi * 2 + r8;
        int gate = q & 3;
        int jhi  = q >> 2;
        int j = cb * 32 + wm * 16 + jhi * 8 + grp;
        int kl = k16 * 16 + khi + 2 * tig;
        const float* src = (kt < 16) ? W : R;
        int k = (kt < 16 ? kt : kt - 16) * 64 + kl;
        int col = gate * 1024 + j;
        ((__half2*)g_WRp)[idx] = __floats2half2_rn(src[(size_t)k * FOURH + col],
                                                   src[(size_t)(k + 1) * FOURH + col]);
    } else if (idx < N1 + N2) {
        int id = idx - N1;
        int grp = id & 7;
        int k16 = (id >> 3) & 3;
        int kt  = (id >> 5) & 15;
        int blk = id >> 9;
        int m = blk * 8 + grp;
        int t = m >> 9, bb = m & 511;
        const float* s = x + ((size_t)bb * TIME_TOT + t) * FEAT + kt * 64 + k16 * 16;
        float f[16];
#pragma unroll
        for (int qd = 0; qd < 4; qd++) *(float4*)(f + qd * 4) = *(const float4*)(s + qd * 4);
        __half2 o[8];
#pragma unroll
        for (int tg = 0; tg < 4; tg++)
#pragma unroll
            for (int rg = 0; rg < 2; rg++)
                o[tg * 2 + rg] = __floats2half2_rn(f[rg * 8 + 2 * tg], f[rg * 8 + 2 * tg + 1]);
        __half2* d = (__half2*)g_xp + (size_t)blk * 4096 + kt * 256 + k16 * 64 + grp * 8;
        *(uint4*)d = *(uint4*)o;
        *(uint4*)(d + 4) = *(uint4*)(o + 4);
    } else if (idx < N1 + N2 + N3) {
        ((uint32_t*)g_hp)[idx - N1 - N2] = 0u;     // zero hp[0]
    } else if (idx < N1 + N2 + N3 + 4) {
        g_sync4[idx - N1 - N2 - N3] = 0u;
    }
}

// ------------------------------ pipeline pieces (512 threads) ------------------
#define ISSUE_STAGE(s, kt, bxp, bhp) do {                                         \
    uint32_t _stA = sb + (uint32_t)(s) * STAGE_B;                                 \
    uint32_t _stB = _stA + 16384u;                                                \
    const char* _as = Abase + (size_t)(kt) * 16384;                               \
    _Pragma("unroll")                                                             \
    for (int _r = 0; _r < 2; _r++) {                                              \
        int _id = tid + _r * NTHR;                                                \
        CP16(_stA + _id * 16, _as + _id * 16);                                    \
    }                                                                             \
    const char* _bsrc = ((kt) < 16) ? ((bxp) + (size_t)(kt) * 1024)               \
                                    : ((bhp) + (size_t)((kt) - 16) * 1024);       \
    _Pragma("unroll")                                                             \
    for (int _r = 0; _r < 2; _r++) {                                              \
        int _id = tid + _r * NTHR;                                                \
        int _bk = _id >> 6, _in = _id & 63;                                       \
        CP16(_stB + _id * 16, _bsrc + (size_t)_bk * 16384 + _in * 16);            \
    }                                                                             \
} while (0)

// warp tile 64x16: wm in {0,1} (A rows, gate-interleaved), wn in {0..7} (16 cols)
#define COMPUTE_STAGE(s) do {                                                     \
    uint32_t _aB = sb + (uint32_t)(s) * STAGE_B + wm * 8192u + grp * 64u + tig * 16u; \
    uint32_t _bB = sb + (uint32_t)(s) * STAGE_B + 16384u + wn * 2048u + grp * 32u + tig * 8u; \
    _Pragma("unroll")                                                             \
    for (int _k = 0; _k < 4; _k++) {                                              \
        uint4 _af[4]; uint2 _bf[2];                                               \
        _Pragma("unroll")                                                         \
        for (int _mi = 0; _mi < 4; _mi++)                                         \
            _af[_mi] = lds128u(_aB + _mi * 2048 + _k * 512);                      \
        _Pragma("unroll")                                                         \
        for (int _nj = 0; _nj < 2; _nj++)                                         \
            _bf[_nj] = lds64u(_bB + _nj * 1024 + _k * 256);                       \
        _Pragma("unroll")                                                         \
        for (int _mi = 0; _mi < 4; _mi++)                                         \
            _Pragma("unroll")                                                     \
            for (int _nj = 0; _nj < 2; _nj++)                                     \
                mma_f16(acc[_mi][_nj], _af[_mi], _bf[_nj]);                       \
    }                                                                             \
} while (0)

// ------------------------------ persistent fused LSTM -------------------------
__global__ void __launch_bounds__(NTHR, 1)
lstm_persist(const float* __restrict__ bias, float* __restrict__ out)
{
    extern __shared__ char smem[];
    const uint32_t sb = (uint32_t)__cvta_generic_to_shared(smem);
    const int tid = threadIdx.x, lane = tid & 31, wid = tid >> 5;
    const int wm = wid >> 3, wn = wid & 7;            // 2 x 8 warp grid
    const int grp = lane >> 2, tig = lane & 3;
    const int cb = blockIdx.x, by = blockIdx.y;

    const char* Abase = (const char*)g_WRp + (size_t)cb * 524288;

    const int j0 = cb * 32 + wm * 16;
    float bia[2][4];
#pragma unroll
    for (int jhi = 0; jhi < 2; jhi++) {
        const int j = j0 + jhi * 8 + grp;
        bia[jhi][0] = __ldg(bias + j);
        bia[jhi][1] = __ldg(bias + 1024 + j);
        bia[jhi][2] = __ldg(bias + 2048 + j);
        bia[jhi][3] = __ldg(bias + 3072 + j);
    }
    float cr[2][2][2];
#pragma unroll
    for (int a = 0; a < 2; a++)
#pragma unroll
        for (int b = 0; b < 2; b++) { cr[a][b][0] = 0.f; cr[a][b][1] = 0.f; }

    // prologue
    {
        const char* Bx = (const char*)g_xp + (size_t)(by * 16) * 16384;
        const char* Bh = (const char*)g_hp[0] + (size_t)(by * 16) * 16384;
        ISSUE_STAGE(0, 0, Bx, Bh); CP_COMMIT();
        ISSUE_STAGE(1, 1, Bx, Bh); CP_COMMIT();
        ISSUE_STAGE(2, 2, Bx, Bh); CP_COMMIT();
    }

    for (int t = 0; t < TSTEPS; t++) {
        const char* Bx  = (const char*)g_xp + (size_t)(t * 64 + by * 16) * 16384;
        const char* Bh  = (const char*)g_hp[t & 1] + (size_t)(by * 16) * 16384;
        const char* BxN = (const char*)g_xp + (size_t)((t + 1) * 64 + by * 16) * 16384;
        __half* hw = g_hp[(t & 1) ^ 1];

        float acc[4][2][4];
#pragma unroll
        for (int a = 0; a < 4; a++)
#pragma unroll
            for (int b = 0; b < 2; b++)
#pragma unroll
                for (int c = 0; c < 4; c++) acc[a][b][c] = 0.f;

        for (int kt = 0; kt < 32; kt++) {
            CP_WAIT2();
            __syncthreads();
            if (kt == 13) {
                if (t > 0 && tid == 0) {
                    const unsigned tgt = (unsigned)t * 32u;
                    while (*(volatile unsigned*)&g_sync4[by] < tgt) { }
                    __threadfence();
                }
                __syncthreads();
            }
            const int la = kt + 3;
            if (la < 32) {
                ISSUE_STAGE(la & 3, la, Bx, Bh);
            } else if (t + 1 < TSTEPS) {
                ISSUE_STAGE(la & 3, la - 32, BxN, Bh);
            }
            CP_COMMIT();
            COMPUTE_STAGE(kt & 3);
        }

        // ---- fused LSTM epilogue ----
        float hnv[2][2][2];
#pragma unroll
        for (int jhi = 0; jhi < 2; jhi++) {
            const int j = j0 + jhi * 8 + grp;
            const int kt_  = j >> 6;
            const int k16_ = (j >> 4) & 3;
            const int reg_ = (j >> 3) & 1;
            const int tig_ = (j >> 1) & 3;
            const int u_   = j & 1;
            const int jbase = (kt_ * 4 + k16_) * 32;
#pragma unroll
            for (int nj = 0; nj < 2; nj++) {
                const int blk = by * 16 + wn * 2 + nj;
#pragma unroll
                for (int e = 0; e < 2; e++) {
                    const int grp_b = tig * 2 + e;
                    float zi = acc[2 * jhi    ][nj][e]     + bia[jhi][0];
                    float zf = acc[2 * jhi    ][nj][2 + e] + bia[jhi][1];
                    float zg = acc[2 * jhi + 1][nj][e]     + bia[jhi][2];
                    float zo = acc[2 * jhi + 1][nj][2 + e] + bia[jhi][3];

                    float si = sigm_f(zi);
                    float sf = sigm_f(zf);
                    float so = sigm_f(zo);
                    float tg = tanh_f(zg);

                    float cn = sf * cr[jhi][nj][e] + si * tg;
                    float hn = so * tanh_f(cn);
                    cr[jhi][nj][e] = cn;
                    hnv[jhi][nj][e] = hn;
                    hw[(size_t)blk * 8192 + (jbase + grp_b * 4 + tig_) * 4 + reg_ * 2 + u_] =
                        __float2half_rn(hn);
                }
            }
        }

        __syncthreads();
        if (tid == 0) {
            __threadfence();
            atomicAdd(&g_sync4[by], 1u);
        }

        // out stores off the critical path
#pragma unroll
        for (int jhi = 0; jhi < 2; jhi++) {
            const int j = j0 + jhi * 8 + grp;
#pragma unroll
            for (int nj = 0; nj < 2; nj++) {
                const int blk = by * 16 + wn * 2 + nj;
#pragma unroll
                for (int e = 0; e < 2; e++) {
                    const int b = blk * 8 + tig * 2 + e;
                    out[(size_t)b * (TSTEPS * HIDDEN) + (size_t)t * 1024 + j] = hnv[jhi][nj][e];
                }
            }
        }
    }
}

// ------------------------------ launch ----------------------------------------
extern "C" void kernel_launch(void* const* d_in, const int* in_sizes, int n_in,
                              void* d_out, int out_size)
{
    const float* x    = (const float*)d_in[0];  // [512, 103, 1024]
    const float* W    = (const float*)d_in[1];  // [1024, 4096]
    const float* R    = (const float*)d_in[2];  // [1024, 4096]
    const float* bias = (const float*)d_in[3];  // [4096]
    float* out = (float*)d_out;                 // [512, 100, 1024]

    cudaFuncSetAttribute(lstm_persist, cudaFuncAttributeMaxDynamicSharedMemorySize, SMEM_SZ);

    const int total = N1 + N2 + N3 + 4;
    prep_all<<<(total + 255) / 256, 256>>>(W, R, x);

    dim3 grid(32, 4);   // 128 CTAs, 1/SM, co-resident
    lstm_persist<<<grid, NTHR, SMEM_SZ>>>(bias, out);
}

// round 10
// speedup vs baseline: 1.2958x; 1.2958x over previous
#include <cuda_runtime.h>
#include <cuda_fp16.h>
#include <cstdint>
#include <math.h>

#define HIDDEN   1024
#define BATCH    512
#define FEAT     1024
#define TSTEPS   100
#define TIME_TOT 103
#define FOURH    4096
#define MTOT     (TSTEPS * BATCH)   // 51200

#define STAGE_B  65536               // A 32KB + B 32KB (BK = 128)
#define NSTAGE   3
#define SMEM_SZ  (NSTAGE * STAGE_B)  // 196608

// ------------------------------ scratch (device globals, no allocs) ----------
__device__ __align__(16) __half g_WRp[32 * 32 * 8192];         // [W;R] fp16 per-strip (16MB)
__device__ __align__(16) __half g_xp[(size_t)MTOT * 1024];     // permuted x fp16 (100MB)
__device__ __align__(16) __half g_hp[2][BATCH * HIDDEN];       // permuted h fp16 ping-pong
__device__ unsigned g_sync4[4];                                // per-by-group barrier counters

// ------------------------------ asm helpers ----------------------------------
#define CP16(dst, src) \
    asm volatile("cp.async.cg.shared.global [%0], [%1], 16;" :: "r"(dst), "l"(src))
#define CP_COMMIT() asm volatile("cp.async.commit_group;" ::: "memory")
#define CP_WAIT1()  asm volatile("cp.async.wait_group 1;" ::: "memory")

__device__ __forceinline__ uint4 lds128u(uint32_t a) {
    uint4 v;
    asm volatile("ld.shared.v4.b32 {%0,%1,%2,%3}, [%4];"
                 : "=r"(v.x), "=r"(v.y), "=r"(v.z), "=r"(v.w) : "r"(a));
    return v;
}
__device__ __forceinline__ uint2 lds64u(uint32_t a) {
    uint2 v;
    asm volatile("ld.shared.v2.b32 {%0,%1}, [%2];" : "=r"(v.x), "=r"(v.y) : "r"(a));
    return v;
}
__device__ __forceinline__ void mma_f16(float c[4], uint4 a, uint2 b) {
    asm volatile(
        "mma.sync.aligned.m16n8k16.row.col.f32.f16.f16.f32 "
        "{%0,%1,%2,%3}, {%4,%5,%6,%7}, {%8,%9}, {%0,%1,%2,%3};"
        : "+f"(c[0]), "+f"(c[1]), "+f"(c[2]), "+f"(c[3])
        : "r"(a.x), "r"(a.y), "r"(a.z), "r"(a.w), "r"(b.x), "r"(b.y));
}

// fast transcendentals
__device__ __forceinline__ float sigm_f(float z) {
    return __fdividef(1.f, 1.f + __expf(-z));
}
__device__ __forceinline__ float tanh_f(float z) {
    return 1.f - __fdividef(2.f, __expf(2.f * z) + 1.f);
}

// ------------------------------ prep (single launch) --------------------------
#define N1 (32 * 32 * 4096)          // WRp half2 elems
#define N2 (MTOT * 1024 / 16)        // xp 16-float chunks
#define N3 (BATCH * HIDDEN / 2)      // hp[0] zero words

__global__ void prep_all(const float* __restrict__ W, const float* __restrict__ R,
                         const float* __restrict__ x)
{
    int idx = blockIdx.x * blockDim.x + threadIdx.x;
    if (idx < N1) {
        int v   = idx & 3;
        int tig = (idx >> 2) & 3;
        int grp = (idx >> 4) & 7;
        int k16 = (idx >> 7) & 3;
        int mi  = (idx >> 9) & 3;
        int wm  = (idx >> 11) & 1;
        int kt  = (idx >> 12) & 31;
        int cb  = idx >> 17;
        int r8  = v & 1;
        int khi = (v >> 1) * 8;
        int q   = mi * 2 + r8;
        int gate = q & 3;
        int jhi  = q >> 2;
        int j = cb * 32 + wm * 16 + jhi * 8 + grp;
        int kl = k16 * 16 + khi + 2 * tig;
        const float* src = (kt < 16) ? W : R;
        int k = (kt < 16 ? kt : kt - 16) * 64 + kl;
        int col = gate * 1024 + j;
        ((__half2*)g_WRp)[idx] = __floats2half2_rn(src[(size_t)k * FOURH + col],
                                                   src[(size_t)(k + 1) * FOURH + col]);
    } else if (idx < N1 + N2) {
        int id = idx - N1;
        int grp = id & 7;
        int k16 = (id >> 3) & 3;
        int kt  = (id >> 5) & 15;
        int blk = id >> 9;
        int m = blk * 8 + grp;
        int t = m >> 9, bb = m & 511;
        const float* s = x + ((size_t)bb * TIME_TOT + t) * FEAT + kt * 64 + k16 * 16;
        float f[16];
#pragma unroll
        for (int qd = 0; qd < 4; qd++) *(float4*)(f + qd * 4) = *(const float4*)(s + qd * 4);
        __half2 o[8];
#pragma unroll
        for (int tg = 0; tg < 4; tg++)
#pragma unroll
            for (int rg = 0; rg < 2; rg++)
                o[tg * 2 + rg] = __floats2half2_rn(f[rg * 8 + 2 * tg], f[rg * 8 + 2 * tg + 1]);
        __half2* d = (__half2*)g_xp + (size_t)blk * 4096 + kt * 256 + k16 * 64 + grp * 8;
        *(uint4*)d = *(uint4*)o;
        *(uint4*)(d + 4) = *(uint4*)(o + 4);
    } else if (idx < N1 + N2 + N3) {
        ((uint32_t*)g_hp)[idx - N1 - N2] = 0u;     // zero hp[0]
    } else if (idx < N1 + N2 + N3 + 4) {
        g_sync4[idx - N1 - N2 - N3] = 0u;
    }
}

// ------------------------------ pipeline pieces (BK = 128) --------------------
// Stage: A (weights) 32KB @ +0, B (activations) 32KB @ +32768.
// ktile K covers k = K*128 .. K*128+127; K<8 = x-phase (W), K>=8 = h-phase (R).
#define ISSUE_STAGE(s, K, bxp, bhp) do {                                          \
    uint32_t _stA = sb + (uint32_t)(s) * STAGE_B;                                 \
    uint32_t _stB = _stA + 32768u;                                                \
    const char* _as = Abase + (size_t)(K) * 32768;                                \
    _Pragma("unroll")                                                             \
    for (int _r = 0; _r < 8; _r++) {                                              \
        int _id = tid + _r * 256;                                                 \
        CP16(_stA + _id * 16, _as + _id * 16);                                    \
    }                                                                             \
    const char* _bsrc = ((K) < 8) ? ((bxp) + (size_t)(K) * 2048)                  \
                                  : ((bhp) + (size_t)((K) - 8) * 2048);           \
    _Pragma("unroll")                                                             \
    for (int _r = 0; _r < 8; _r++) {                                              \
        int _c = tid + _r * 256;                                                  \
        int _blk = _c >> 7, _in = _c & 127;                                       \
        CP16(_stB + _c * 16, _bsrc + (size_t)_blk * 16384 + _in * 16);            \
    }                                                                             \
} while (0)

// warp tile 64x32 (wm in {0,1}, wn in {0..3}); 8 k16 sub-iterations per ktile.
// A stage layout: [sub(2):16384][wm:8192][mi:2048][k16:512][grp:64][tig:16]
// B stage layout: [blk(16):2048][sub(2):1024][k16:256][grp:32][tig:8]
#define COMPUTE_STAGE(s) do {                                                     \
    uint32_t _aB = sb + (uint32_t)(s) * STAGE_B + wm * 8192u + grp * 64u + tig * 16u; \
    uint32_t _bB = sb + (uint32_t)(s) * STAGE_B + 32768u + wn * 8192u + grp * 32u + tig * 8u; \
    _Pragma("unroll")                                                             \
    for (int _k = 0; _k < 8; _k++) {                                              \
        const uint32_t _ao = (_k >> 2) * 16384u + (_k & 3) * 512u;                \
        const uint32_t _bo = (_k >> 2) * 1024u  + (_k & 3) * 256u;                \
        uint4 _af[4]; uint2 _bf[4];                                               \
        _Pragma("unroll")                                                         \
        for (int _mi = 0; _mi < 4; _mi++)                                         \
            _af[_mi] = lds128u(_aB + _ao + _mi * 2048);                           \
        _Pragma("unroll")                                                         \
        for (int _nj = 0; _nj < 4; _nj++)                                         \
            _bf[_nj] = lds64u(_bB + _bo + _nj * 2048);                            \
        _Pragma("unroll")                                                         \
        for (int _mi = 0; _mi < 4; _mi++)                                         \
            _Pragma("unroll")                                                     \
            for (int _nj = 0; _nj < 4; _nj++)                                     \
                mma_f16(acc[_mi][_nj], _af[_mi], _bf[_nj]);                       \
    }                                                                             \
} while (0)

// ------------------------------ persistent fused LSTM -------------------------
// grid (32,4): cb = 32-hidden strip, by = 128-batch block. 1 CTA/SM, resident.
// STAGE PHASE FIX (r9 bug): 16 ktiles/step with 3 stages => phase shifts by
// 16 mod 3 = 1 per step. Stage of local ktile kt at step t is (t + kt) % 3,
// matching the GLOBAL ktile counter (16t + kt) mod 3.
__global__ void __launch_bounds__(256, 1)
lstm_persist(const float* __restrict__ bias, float* __restrict__ out)
{
    extern __shared__ char smem[];
    const uint32_t sb = (uint32_t)__cvta_generic_to_shared(smem);
    const int tid = threadIdx.x, lane = tid & 31, wid = tid >> 5;
    const int wm = wid >> 2, wn = wid & 3;
    const int grp = lane >> 2, tig = lane & 3;
    const int cb = blockIdx.x, by = blockIdx.y;

    const char* Abase = (const char*)g_WRp + (size_t)cb * 524288;

    const int j0 = cb * 32 + wm * 16;
    float bia[2][4];
#pragma unroll
    for (int jhi = 0; jhi < 2; jhi++) {
        const int j = j0 + jhi * 8 + grp;
        bia[jhi][0] = __ldg(bias + j);
        bia[jhi][1] = __ldg(bias + 1024 + j);
        bia[jhi][2] = __ldg(bias + 2048 + j);
        bia[jhi][3] = __ldg(bias + 3072 + j);
    }
    float cr[2][4][2];
#pragma unroll
    for (int a = 0; a < 2; a++)
#pragma unroll
        for (int b = 0; b < 4; b++) { cr[a][b][0] = 0.f; cr[a][b][1] = 0.f; }

    // prologue: global ktiles 0,1 (t=0, x-phase) -> stages 0,1
    {
        const char* Bx = (const char*)g_xp + (size_t)(by * 16) * 16384;
        const char* Bh = (const char*)g_hp[0] + (size_t)(by * 16) * 16384;
        ISSUE_STAGE(0, 0, Bx, Bh); CP_COMMIT();
        ISSUE_STAGE(1, 1, Bx, Bh); CP_COMMIT();
    }

    for (int t = 0; t < TSTEPS; t++) {
        const char* Bx  = (const char*)g_xp + (size_t)(t * 64 + by * 16) * 16384;
        const char* Bh  = (const char*)g_hp[t & 1] + (size_t)(by * 16) * 16384;
        const char* BxN = (const char*)g_xp + (size_t)((t + 1) * 64 + by * 16) * 16384;
        __half* hw = g_hp[(t & 1) ^ 1];
        const int ph = t % 3;                  // stage phase of this step

        float acc[4][4][4];
#pragma unroll
        for (int a = 0; a < 4; a++)
#pragma unroll
            for (int b = 0; b < 4; b++)
#pragma unroll
                for (int c = 0; c < 4; c++) acc[a][b][c] = 0.f;

        for (int kt = 0; kt < 16; kt++) {
            CP_WAIT1();
            __syncthreads();
            if (kt == 6) {
                // h of this step becomes an issue-dependency at ktile 8
                if (t > 0 && tid == 0) {
                    const unsigned tgt = (unsigned)t * 32u;
                    while (*(volatile unsigned*)&g_sync4[by] < tgt) { }
                    __threadfence();
                }
                __syncthreads();
            }
            const int la = kt + 2;
            const int is = (ph + la) % 3;          // GLOBAL-phase stage index
            if (la < 16) {
                ISSUE_STAGE(is, la, Bx, Bh);
            } else if (t + 1 < TSTEPS) {
                ISSUE_STAGE(is, la - 16, BxN, Bh); // next step's x ktiles 0,1
            }
            CP_COMMIT();
            COMPUTE_STAGE((ph + kt) % 3);
        }

        // ---- fused LSTM epilogue (c in registers) ----
        float hnv[2][4][2];
#pragma unroll
        for (int jhi = 0; jhi < 2; jhi++) {
            const int j = j0 + jhi * 8 + grp;
            const int kt_  = j >> 6;
            const int k16_ = (j >> 4) & 3;
            const int reg_ = (j >> 3) & 1;
            const int tig_ = (j >> 1) & 3;
            const int u_   = j & 1;
            const int jbase = (kt_ * 4 + k16_) * 32;
#pragma unroll
            for (int nj = 0; nj < 4; nj++) {
                const int blk = by * 16 + wn * 4 + nj;
#pragma unroll
                for (int e = 0; e < 2; e++) {
                    const int grp_b = tig * 2 + e;
                    float zi = acc[2 * jhi    ][nj][e]     + bia[jhi][0];
                    float zf = acc[2 * jhi    ][nj][2 + e] + bia[jhi][1];
                    float zg = acc[2 * jhi + 1][nj][e]     + bia[jhi][2];
                    float zo = acc[2 * jhi + 1][nj][2 + e] + bia[jhi][3];

                    float si = sigm_f(zi);
                    float sf = sigm_f(zf);
                    float so = sigm_f(zo);
                    float tg = tanh_f(zg);

                    float cn = sf * cr[jhi][nj][e] + si * tg;
                    float hn = so * tanh_f(cn);
                    cr[jhi][nj][e] = cn;
                    hnv[jhi][nj][e] = hn;
                    hw[(size_t)blk * 8192 + (jbase + grp_b * 4 + tig_) * 4 + reg_ * 2 + u_] =
                        __float2half_rn(hn);
                }
            }
        }

        // publish h, arrive, then out stores (off the h critical path)
        __syncthreads();
        if (tid == 0) {
            __threadfence();
            atomicAdd(&g_sync4[by], 1u);
        }

#pragma unroll
        for (int jhi = 0; jhi < 2; jhi++) {
            const int j = j0 + jhi * 8 + grp;
#pragma unroll
            for (int nj = 0; nj < 4; nj++) {
                const int blk = by * 16 + wn * 4 + nj;
#pragma unroll
                for (int e = 0; e < 2; e++) {
                    const int b = blk * 8 + tig * 2 + e;
                    out[(size_t)b * (TSTEPS * HIDDEN) + (size_t)t * 1024 + j] = hnv[jhi][nj][e];
                }
            }
        }
    }
}

// ------------------------------ launch ----------------------------------------
extern "C" void kernel_launch(void* const* d_in, const int* in_sizes, int n_in,
                              void* d_out, int out_size)
{
    const float* x    = (const float*)d_in[0];  // [512, 103, 1024]
    const float* W    = (const float*)d_in[1];  // [1024, 4096]
    const float* R    = (const float*)d_in[2];  // [1024, 4096]
    const float* bias = (const float*)d_in[3];  // [4096]
    float* out = (float*)d_out;                 // [512, 100, 1024]

    cudaFuncSetAttribute(lstm_persist, cudaFuncAttributeMaxDynamicSharedMemorySize, SMEM_SZ);

    const int total = N1 + N2 + N3 + 4;
    prep_all<<<(total + 255) / 256, 256>>>(W, R, x);

    dim3 grid(32, 4);   // 128 CTAs, 1/SM, co-resident
    lstm_persist<<<grid, 256, SMEM_SZ>>>(bias, out);
}

// round 11
// speedup vs baseline: 1.3073x; 1.0089x over previous
#include <cuda_runtime.h>
#include <cuda_fp16.h>
#include <cstdint>
#include <math.h>

#define HIDDEN   1024
#define BATCH    512
#define FEAT     1024
#define TSTEPS   100
#define TIME_TOT 103
#define FOURH    4096
#define MTOT     (TSTEPS * BATCH)   // 51200

#define STAGE_B  65536               // A 32KB + B 32KB (BK = 128)
#define NSTAGE   3
#define SMEM_SZ  (NSTAGE * STAGE_B)  // 196608

// ------------------------------ scratch (device globals, no allocs) ----------
__device__ __align__(16) __half g_WRp[32 * 32 * 8192];         // [W;R] fp16 per-strip (16MB)
__device__ __align__(16) __half g_xp[(size_t)MTOT * 1024];     // permuted x fp16 (100MB)
__device__ __align__(16) __half g_hp[2][BATCH * HIDDEN];       // permuted h fp16 ping-pong
__device__ unsigned g_sync4[4];                                // per-by-group barrier counters

// ------------------------------ asm helpers ----------------------------------
#define CP16(dst, src) \
    asm volatile("cp.async.cg.shared.global [%0], [%1], 16;" :: "r"(dst), "l"(src))
#define CP_COMMIT() asm volatile("cp.async.commit_group;" ::: "memory")
#define CP_WAIT1()  asm volatile("cp.async.wait_group 1;" ::: "memory")

__device__ __forceinline__ uint4 lds128u(uint32_t a) {
    uint4 v;
    asm volatile("ld.shared.v4.b32 {%0,%1,%2,%3}, [%4];"
                 : "=r"(v.x), "=r"(v.y), "=r"(v.z), "=r"(v.w) : "r"(a));
    return v;
}
__device__ __forceinline__ uint2 lds64u(uint32_t a) {
    uint2 v;
    asm volatile("ld.shared.v2.b32 {%0,%1}, [%2];" : "=r"(v.x), "=r"(v.y) : "r"(a));
    return v;
}
__device__ __forceinline__ void mma_f16(float c[4], uint4 a, uint2 b) {
    asm volatile(
        "mma.sync.aligned.m16n8k16.row.col.f32.f16.f16.f32 "
        "{%0,%1,%2,%3}, {%4,%5,%6,%7}, {%8,%9}, {%0,%1,%2,%3};"
        : "+f"(c[0]), "+f"(c[1]), "+f"(c[2]), "+f"(c[3])
        : "r"(a.x), "r"(a.y), "r"(a.z), "r"(a.w), "r"(b.x), "r"(b.y));
}

// fast transcendentals
__device__ __forceinline__ float sigm_f(float z) {
    return __fdividef(1.f, 1.f + __expf(-z));
}
__device__ __forceinline__ float tanh_f(float z) {
    return 1.f - __fdividef(2.f, __expf(2.f * z) + 1.f);
}

// ------------------------------ prep (single launch) --------------------------
#define N1 (32 * 32 * 4096)          // WRp half2 elems
#define N2 (MTOT * 1024 / 16)        // xp 16-float chunks
#define N3 (BATCH * HIDDEN / 2)      // hp[0] zero words

__global__ void prep_all(const float* __restrict__ W, const float* __restrict__ R,
                         const float* __restrict__ x)
{
    int idx = blockIdx.x * blockDim.x + threadIdx.x;
    if (idx < N1) {
        int v   = idx & 3;
        int tig = (idx >> 2) & 3;
        int grp = (idx >> 4) & 7;
        int k16 = (idx >> 7) & 3;
        int mi  = (idx >> 9) & 3;
        int wm  = (idx >> 11) & 1;
        int kt  = (idx >> 12) & 31;
        int cb  = idx >> 17;
        int r8  = v & 1;
        int khi = (v >> 1) * 8;
        int q   = mi * 2 + r8;
        int gate = q & 3;
        int jhi  = q >> 2;
        int j = cb * 32 + wm * 16 + jhi * 8 + grp;
        int kl = k16 * 16 + khi + 2 * tig;
        const float* src = (kt < 16) ? W : R;
        int k = (kt < 16 ? kt : kt - 16) * 64 + kl;
        int col = gate * 1024 + j;
        ((__half2*)g_WRp)[idx] = __floats2half2_rn(src[(size_t)k * FOURH + col],
                                                   src[(size_t)(k + 1) * FOURH + col]);
    } else if (idx < N1 + N2) {
        int id = idx - N1;
        int grp = id & 7;
        int k16 = (id >> 3) & 3;
        int kt  = (id >> 5) & 15;
        int blk = id >> 9;
        int m = blk * 8 + grp;
        int t = m >> 9, bb = m & 511;
        const float* s = x + ((size_t)bb * TIME_TOT + t) * FEAT + kt * 64 + k16 * 16;
        float f[16];
#pragma unroll
        for (int qd = 0; qd < 4; qd++) *(float4*)(f + qd * 4) = *(const float4*)(s + qd * 4);
        __half2 o[8];
#pragma unroll
        for (int tg = 0; tg < 4; tg++)
#pragma unroll
            for (int rg = 0; rg < 2; rg++)
                o[tg * 2 + rg] = __floats2half2_rn(f[rg * 8 + 2 * tg], f[rg * 8 + 2 * tg + 1]);
        __half2* d = (__half2*)g_xp + (size_t)blk * 4096 + kt * 256 + k16 * 64 + grp * 8;
        *(uint4*)d = *(uint4*)o;
        *(uint4*)(d + 4) = *(uint4*)(o + 4);
    } else if (idx < N1 + N2 + N3) {
        ((uint32_t*)g_hp)[idx - N1 - N2] = 0u;     // zero hp[0]
    } else if (idx < N1 + N2 + N3 + 4) {
        g_sync4[idx - N1 - N2 - N3] = 0u;
    }
}

// ------------------------------ pipeline pieces (BK = 128) --------------------
// Stage: A (weights) 32KB @ +0, B (activations) 32KB @ +32768.
// ktile K covers k = K*128 .. K*128+127; K<8 = x-phase (W), K>=8 = h-phase (R).
#define ISSUE_STAGE(s, K, bxp, bhp) do {                                          \
    uint32_t _stA = sb + (uint32_t)(s) * STAGE_B;                                 \
    uint32_t _stB = _stA + 32768u;                                                \
    const char* _as = Abase + (size_t)(K) * 32768;                                \
    _Pragma("unroll")                                                             \
    for (int _r = 0; _r < 8; _r++) {                                              \
        int _id = tid + _r * 256;                                                 \
        CP16(_stA + _id * 16, _as + _id * 16);                                    \
    }                                                                             \
    const char* _bsrc = ((K) < 8) ? ((bxp) + (size_t)(K) * 2048)                  \
                                  : ((bhp) + (size_t)((K) - 8) * 2048);           \
    _Pragma("unroll")                                                             \
    for (int _r = 0; _r < 8; _r++) {                                              \
        int _c = tid + _r * 256;                                                  \
        int _blk = _c >> 7, _in = _c & 127;                                       \
        CP16(_stB + _c * 16, _bsrc + (size_t)_blk * 16384 + _in * 16);            \
    }                                                                             \
} while (0)

// warp tile 64x32 (wm in {0,1}, wn in {0..3}); 8 k16 sub-iterations per ktile.
// Fragments explicitly DOUBLE-BUFFERED in registers: prefetch k+1 while k's
// MMAs issue — forces LDS->MMA overlap instead of relying on ptxas scheduling.
// A stage layout: [sub(2):16384][wm:8192][mi:2048][k16:512][grp:64][tig:16]
// B stage layout: [blk(16):2048][sub(2):1024][k16:256][grp:32][tig:8]
#define COMPUTE_STAGE(s) do {                                                     \
    uint32_t _aB = sb + (uint32_t)(s) * STAGE_B + wm * 8192u + grp * 64u + tig * 16u; \
    uint32_t _bB = sb + (uint32_t)(s) * STAGE_B + 32768u + wn * 8192u + grp * 32u + tig * 8u; \
    uint4 _af[2][4]; uint2 _bf[2][4];                                             \
    _Pragma("unroll")                                                             \
    for (int _mi = 0; _mi < 4; _mi++) _af[0][_mi] = lds128u(_aB + _mi * 2048);    \
    _Pragma("unroll")                                                             \
    for (int _nj = 0; _nj < 4; _nj++) _bf[0][_nj] = lds64u(_bB + _nj * 2048);     \
    _Pragma("unroll")                                                             \
    for (int _k = 0; _k < 8; _k++) {                                              \
        const int _cur = _k & 1, _nxt = _cur ^ 1;                                 \
        if (_k < 7) {                                                             \
            const uint32_t _ao = ((_k + 1) >> 2) * 16384u + ((_k + 1) & 3) * 512u; \
            const uint32_t _bo = ((_k + 1) >> 2) * 1024u  + ((_k + 1) & 3) * 256u; \
            _Pragma("unroll")                                                     \
            for (int _mi = 0; _mi < 4; _mi++)                                     \
                _af[_nxt][_mi] = lds128u(_aB + _ao + _mi * 2048);                 \
            _Pragma("unroll")                                                     \
            for (int _nj = 0; _nj < 4; _nj++)                                     \
                _bf[_nxt][_nj] = lds64u(_bB + _bo + _nj * 2048);                  \
        }                                                                         \
        _Pragma("unroll")                                                         \
        for (int _mi = 0; _mi < 4; _mi++)                                         \
            _Pragma("unroll")                                                     \
            for (int _nj = 0; _nj < 4; _nj++)                                     \
                mma_f16(acc[_mi][_nj], _af[_cur][_mi], _bf[_cur][_nj]);           \
    }                                                                             \
} while (0)

// ------------------------------ persistent fused LSTM -------------------------
// grid (32,4): cb = 32-hidden strip, by = 128-batch block. 1 CTA/SM, resident.
// Stage of local ktile kt at step t is (t + kt) % 3 (global ktile counter).
__global__ void __launch_bounds__(256, 1)
lstm_persist(const float* __restrict__ bias, float* __restrict__ out)
{
    extern __shared__ char smem[];
    const uint32_t sb = (uint32_t)__cvta_generic_to_shared(smem);
    const int tid = threadIdx.x, lane = tid & 31, wid = tid >> 5;
    const int wm = wid >> 2, wn = wid & 3;
    const int grp = lane >> 2, tig = lane & 3;
    const int cb = blockIdx.x, by = blockIdx.y;

    const char* Abase = (const char*)g_WRp + (size_t)cb * 524288;

    const int j0 = cb * 32 + wm * 16;
    float bia[2][4];
#pragma unroll
    for (int jhi = 0; jhi < 2; jhi++) {
        const int j = j0 + jhi * 8 + grp;
        bia[jhi][0] = __ldg(bias + j);
        bia[jhi][1] = __ldg(bias + 1024 + j);
        bia[jhi][2] = __ldg(bias + 2048 + j);
        bia[jhi][3] = __ldg(bias + 3072 + j);
    }
    float cr[2][4][2];
#pragma unroll
    for (int a = 0; a < 2; a++)
#pragma unroll
        for (int b = 0; b < 4; b++) { cr[a][b][0] = 0.f; cr[a][b][1] = 0.f; }

    // prologue: global ktiles 0,1 (t=0, x-phase) -> stages 0,1
    {
        const char* Bx = (const char*)g_xp + (size_t)(by * 16) * 16384;
        const char* Bh = (const char*)g_hp[0] + (size_t)(by * 16) * 16384;
        ISSUE_STAGE(0, 0, Bx, Bh); CP_COMMIT();
        ISSUE_STAGE(1, 1, Bx, Bh); CP_COMMIT();
    }

    for (int t = 0; t < TSTEPS; t++) {
        const char* Bx  = (const char*)g_xp + (size_t)(t * 64 + by * 16) * 16384;
        const char* Bh  = (const char*)g_hp[t & 1] + (size_t)(by * 16) * 16384;
        const char* BxN = (const char*)g_xp + (size_t)((t + 1) * 64 + by * 16) * 16384;
        __half* hw = g_hp[(t & 1) ^ 1];
        const int ph = t % 3;                  // stage phase of this step

        float acc[4][4][4];
#pragma unroll
        for (int a = 0; a < 4; a++)
#pragma unroll
            for (int b = 0; b < 4; b++)
#pragma unroll
                for (int c = 0; c < 4; c++) acc[a][b][c] = 0.f;

        for (int kt = 0; kt < 16; kt++) {
            CP_WAIT1();
            __syncthreads();
            if (kt == 6 && t > 0) {
                // first h-dependent issue happens THIS iteration (la = 8).
                // All threads spin on the group counter — no extra CTA barriers.
                const unsigned tgt = (unsigned)t * 32u;
                while (*(volatile unsigned*)&g_sync4[by] < tgt) { }
                __threadfence();
            }
            const int la = kt + 2;
            const int is = (ph + la) % 3;          // GLOBAL-phase stage index
            if (la < 16) {
                ISSUE_STAGE(is, la, Bx, Bh);
            } else if (t + 1 < TSTEPS) {
                ISSUE_STAGE(is, la - 16, BxN, Bh); // next step's x ktiles 0,1
            }
            CP_COMMIT();
            COMPUTE_STAGE((ph + kt) % 3);
        }

        // ---- fused LSTM epilogue (c in registers) ----
        float hnv[2][4][2];
#pragma unroll
        for (int jhi = 0; jhi < 2; jhi++) {
            const int j = j0 + jhi * 8 + grp;
            const int kt_  = j >> 6;
            const int k16_ = (j >> 4) & 3;
            const int reg_ = (j >> 3) & 1;
            const int tig_ = (j >> 1) & 3;
            const int u_   = j & 1;
            const int jbase = (kt_ * 4 + k16_) * 32;
#pragma unroll
            for (int nj = 0; nj < 4; nj++) {
                const int blk = by * 16 + wn * 4 + nj;
#pragma unroll
                for (int e = 0; e < 2; e++) {
                    const int grp_b = tig * 2 + e;
                    float zi = acc[2 * jhi    ][nj][e]     + bia[jhi][0];
                    float zf = acc[2 * jhi    ][nj][2 + e] + bia[jhi][1];
                    float zg = acc[2 * jhi + 1][nj][e]     + bia[jhi][2];
                    float zo = acc[2 * jhi + 1][nj][2 + e] + bia[jhi][3];

                    float si = sigm_f(zi);
                    float sf = sigm_f(zf);
                    float so = sigm_f(zo);
                    float tg = tanh_f(zg);

                    float cn = sf * cr[jhi][nj][e] + si * tg;
                    float hn = so * tanh_f(cn);
                    cr[jhi][nj][e] = cn;
                    hnv[jhi][nj][e] = hn;
                    hw[(size_t)blk * 8192 + (jbase + grp_b * 4 + tig_) * 4 + reg_ * 2 + u_] =
                        __float2half_rn(hn);
                }
            }
        }

        // publish h, arrive, then out stores (off the h critical path)
        __syncthreads();
        if (tid == 0) {
            __threadfence();
            atomicAdd(&g_sync4[by], 1u);
        }

#pragma unroll
        for (int jhi = 0; jhi < 2; jhi++) {
            const int j = j0 + jhi * 8 + grp;
#pragma unroll
            for (int nj = 0; nj < 4; nj++) {
                const int blk = by * 16 + wn * 4 + nj;
#pragma unroll
                for (int e = 0; e < 2; e++) {
                    const int b = blk * 8 + tig * 2 + e;
                    out[(size_t)b * (TSTEPS * HIDDEN) + (size_t)t * 1024 + j] = hnv[jhi][nj][e];
                }
            }
        }
    }
}

// ------------------------------ launch ----------------------------------------
extern "C" void kernel_launch(void* const* d_in, const int* in_sizes, int n_in,
                              void* d_out, int out_size)
{
    const float* x    = (const float*)d_in[0];  // [512, 103, 1024]
    const float* W    = (const float*)d_in[1];  // [1024, 4096]
    const float* R    = (const float*)d_in[2];  // [1024, 4096]
    const float* bias = (const float*)d_in[3];  // [4096]
    float* out = (float*)d_out;                 // [512, 100, 1024]

    cudaFuncSetAttribute(lstm_persist, cudaFuncAttributeMaxDynamicSharedMemorySize, SMEM_SZ);

    const int total = N1 + N2 + N3 + 4;
    prep_all<<<(total + 255) / 256, 256>>>(W, R, x);

    dim3 grid(32, 4);   // 128 CTAs, 1/SM, co-resident
    lstm_persist<<<grid, 256, SMEM_SZ>>>(bias, out);
}

// round 12
// speedup vs baseline: 1.3415x; 1.0261x over previous
#include <cuda_runtime.h>
#include <cuda_fp16.h>
#include <cstdint>
#include <math.h>

#define HIDDEN   1024
#define BATCH    512
#define FEAT     1024
#define TSTEPS   100
#define TIME_TOT 103
#define FOURH    4096
#define MTOT     (TSTEPS * BATCH)   // 51200

// per group: 2 stages x (A 32KB + B 16KB) = 96KB; two groups = 192KB
#define STG_B    49152
#define GRP_B    98304
#define SMEM_SZ  196608

// ------------------------------ scratch (device globals, no allocs) ----------
__device__ __align__(16) __half g_WRp[32 * 32 * 8192];         // [W;R] fp16 per-strip (16MB)
__device__ __align__(16) __half g_xp[(size_t)MTOT * 1024];     // permuted x fp16 (100MB)
__device__ __align__(16) __half g_hp[2][BATCH * HIDDEN];       // permuted h fp16 ping-pong
__device__ unsigned g_sync8[8];                                // per-(by,group) counters

// ------------------------------ asm helpers ----------------------------------
#define CP16(dst, src) \
    asm volatile("cp.async.cg.shared.global [%0], [%1], 16;" :: "r"(dst), "l"(src))
#define CP_COMMIT() asm volatile("cp.async.commit_group;" ::: "memory")
#define CP_WAIT1()  asm volatile("cp.async.wait_group 1;" ::: "memory")
#define BARG()      asm volatile("bar.sync %0, 128;" :: "r"(barid) : "memory")

__device__ __forceinline__ uint4 lds128u(uint32_t a) {
    uint4 v;
    asm volatile("ld.shared.v4.b32 {%0,%1,%2,%3}, [%4];"
                 : "=r"(v.x), "=r"(v.y), "=r"(v.z), "=r"(v.w) : "r"(a));
    return v;
}
__device__ __forceinline__ uint2 lds64u(uint32_t a) {
    uint2 v;
    asm volatile("ld.shared.v2.b32 {%0,%1}, [%2];" : "=r"(v.x), "=r"(v.y) : "r"(a));
    return v;
}
__device__ __forceinline__ void mma_f16(float c[4], uint4 a, uint2 b) {
    asm volatile(
        "mma.sync.aligned.m16n8k16.row.col.f32.f16.f16.f32 "
        "{%0,%1,%2,%3}, {%4,%5,%6,%7}, {%8,%9}, {%0,%1,%2,%3};"
        : "+f"(c[0]), "+f"(c[1]), "+f"(c[2]), "+f"(c[3])
        : "r"(a.x), "r"(a.y), "r"(a.z), "r"(a.w), "r"(b.x), "r"(b.y));
}

// fast transcendentals
__device__ __forceinline__ float sigm_f(float z) {
    return __fdividef(1.f, 1.f + __expf(-z));
}
__device__ __forceinline__ float tanh_f(float z) {
    return 1.f - __fdividef(2.f, __expf(2.f * z) + 1.f);
}

// ------------------------------ prep (single launch) --------------------------
#define N1 (32 * 32 * 4096)          // WRp half2 elems
#define N2 (MTOT * 1024 / 16)        // xp 16-float chunks
#define N3 (BATCH * HIDDEN / 2)      // hp[0] zero words

__global__ void prep_all(const float* __restrict__ W, const float* __restrict__ R,
                         const float* __restrict__ x)
{
    int idx = blockIdx.x * blockDim.x + threadIdx.x;
    if (idx < N1) {
        int v   = idx & 3;
        int tig = (idx >> 2) & 3;
        int grp = (idx >> 4) & 7;
        int k16 = (idx >> 7) & 3;
        int mi  = (idx >> 9) & 3;
        int wm  = (idx >> 11) & 1;
        int kt  = (idx >> 12) & 31;
        int cb  = idx >> 17;
        int r8  = v & 1;
        int khi = (v >> 1) * 8;
        int q   = mi * 2 + r8;
        int gate = q & 3;
        int jhi  = q >> 2;
        int j = cb * 32 + wm * 16 + jhi * 8 + grp;
        int kl = k16 * 16 + khi + 2 * tig;
        const float* src = (kt < 16) ? W : R;
        int k = (kt < 16 ? kt : kt - 16) * 64 + kl;
        int col = gate * 1024 + j;
        ((__half2*)g_WRp)[idx] = __floats2half2_rn(src[(size_t)k * FOURH + col],
                                                   src[(size_t)(k + 1) * FOURH + col]);
    } else if (idx < N1 + N2) {
        int id = idx - N1;
        int grp = id & 7;
        int k16 = (id >> 3) & 3;
        int kt  = (id >> 5) & 15;
        int blk = id >> 9;
        int m = blk * 8 + grp;
        int t = m >> 9, bb = m & 511;
        const float* s = x + ((size_t)bb * TIME_TOT + t) * FEAT + kt * 64 + k16 * 16;
        float f[16];
#pragma unroll
        for (int qd = 0; qd < 4; qd++) *(float4*)(f + qd * 4) = *(const float4*)(s + qd * 4);
        __half2 o[8];
#pragma unroll
        for (int tg = 0; tg < 4; tg++)
#pragma unroll
            for (int rg = 0; rg < 2; rg++)
                o[tg * 2 + rg] = __floats2half2_rn(f[rg * 8 + 2 * tg], f[rg * 8 + 2 * tg + 1]);
        __half2* d = (__half2*)g_xp + (size_t)blk * 4096 + kt * 256 + k16 * 64 + grp * 8;
        *(uint4*)d = *(uint4*)o;
        *(uint4*)(d + 4) = *(uint4*)(o + 4);
    } else if (idx < N1 + N2 + N3) {
        ((uint32_t*)g_hp)[idx - N1 - N2] = 0u;     // zero hp[0]
    } else if (idx < N1 + N2 + N3 + 8) {
        g_sync8[idx - N1 - N2 - N3] = 0u;
    }
}

// ------------------------------ per-group pipeline pieces ---------------------
// Group stage: A (weights) 32KB @ +0, B (activations, 64 batch) 16KB @ +32768.
// ktile K covers k = K*128..K*128+127; K<8 = x-phase, K>=8 = h-phase.
// 128 threads (tid2) issue; 4 warps compute (wm in {0,1}, wn in {0,1}).
#define ISSUE_STAGE(s, K, bxp, bhp) do {                                          \
    uint32_t _stA = gbase + (uint32_t)(s) * STG_B;                                \
    uint32_t _stB = _stA + 32768u;                                                \
    const char* _as = Abase + (size_t)(K) * 32768;                                \
    _Pragma("unroll")                                                             \
    for (int _r = 0; _r < 16; _r++) {                                             \
        int _id = tid2 + _r * 128;                                                \
        CP16(_stA + _id * 16, _as + _id * 16);                                    \
    }                                                                             \
    const char* _bsrc = ((K) < 8) ? ((bxp) + (size_t)(K) * 2048)                  \
                                  : ((bhp) + (size_t)((K) - 8) * 2048);           \
    _Pragma("unroll")                                                             \
    for (int _r = 0; _r < 8; _r++) {                                              \
        int _c = tid2 + _r * 128;                                                 \
        CP16(_stB + _c * 16,                                                      \
             _bsrc + (size_t)(_c >> 7) * 16384 + (size_t)(_c & 127) * 16);        \
    }                                                                             \
} while (0)

// A: [sub(2):16384][wm:8192][mi:2048][k16:512][grp:64][tig:16]
// B: [blk(8):2048][sub(2):1024][k16:256][grp:32][tig:8]; warp covers wn*4+nj blks
#define COMPUTE_STAGE(s) do {                                                     \
    uint32_t _aB = gbase + (uint32_t)(s) * STG_B + wm * 8192u + grp * 64u + tig * 16u; \
    uint32_t _bB = gbase + (uint32_t)(s) * STG_B + 32768u + wn * 8192u + grp * 32u + tig * 8u; \
    uint4 _af[2][4]; uint2 _bf[2][4];                                             \
    _Pragma("unroll")                                                             \
    for (int _mi = 0; _mi < 4; _mi++) _af[0][_mi] = lds128u(_aB + _mi * 2048);    \
    _Pragma("unroll")                                                             \
    for (int _nj = 0; _nj < 4; _nj++) _bf[0][_nj] = lds64u(_bB + _nj * 2048);     \
    _Pragma("unroll")                                                             \
    for (int _k = 0; _k < 8; _k++) {                                              \
        const int _cur = _k & 1, _nxt = _cur ^ 1;                                 \
        if (_k < 7) {                                                             \
            const uint32_t _ao = ((_k + 1) >> 2) * 16384u + ((_k + 1) & 3) * 512u; \
            const uint32_t _bo = ((_k + 1) >> 2) * 1024u  + ((_k + 1) & 3) * 256u; \
            _Pragma("unroll")                                                     \
            for (int _mi = 0; _mi < 4; _mi++)                                     \
                _af[_nxt][_mi] = lds128u(_aB + _ao + _mi * 2048);                 \
            _Pragma("unroll")                                                     \
            for (int _nj = 0; _nj < 4; _nj++)                                     \
                _bf[_nxt][_nj] = lds64u(_bB + _bo + _nj * 2048);                  \
        }                                                                         \
        _Pragma("unroll")                                                         \
        for (int _mi = 0; _mi < 4; _mi++)                                         \
            _Pragma("unroll")                                                     \
            for (int _nj = 0; _nj < 4; _nj++)                                     \
                mma_f16(acc[_mi][_nj], _af[_cur][_mi], _bf[_cur][_nj]);           \
    }                                                                             \
} while (0)

// ------------------------------ persistent fused LSTM -------------------------
// grid (32,4). Each CTA = TWO independent 64-batch streams (warps 0-3 / 4-7),
// each with its own 2-stage pipeline, named barrier, and h-sync group.
__global__ void __launch_bounds__(256, 1)
lstm_persist(const float* __restrict__ bias, float* __restrict__ out)
{
    extern __shared__ char smem[];
    const uint32_t sb = (uint32_t)__cvta_generic_to_shared(smem);
    const int tid = threadIdx.x, lane = tid & 31;
    const int g    = tid >> 7;           // stream 0 / 1
    const int tid2 = tid & 127;
    const int wid2 = tid2 >> 5;          // warp within stream: 0..3
    const int wm = wid2 >> 1, wn = wid2 & 1;
    const int grp = lane >> 2, tig = lane & 3;
    const int cb = blockIdx.x, by = blockIdx.y;
    const uint32_t gbase = sb + (uint32_t)g * GRP_B;
    const int barid = 1 + g;
    const int syncIdx = by * 2 + g;

    const char* Abase = (const char*)g_WRp + (size_t)cb * 524288;

    const int j0 = cb * 32 + wm * 16;
    float bia[2][4];
#pragma unroll
    for (int jhi = 0; jhi < 2; jhi++) {
        const int j = j0 + jhi * 8 + grp;
        bia[jhi][0] = __ldg(bias + j);
        bia[jhi][1] = __ldg(bias + 1024 + j);
        bia[jhi][2] = __ldg(bias + 2048 + j);
        bia[jhi][3] = __ldg(bias + 3072 + j);
    }
    float cr[2][4][2];
#pragma unroll
    for (int a = 0; a < 2; a++)
#pragma unroll
        for (int b = 0; b < 4; b++) { cr[a][b][0] = 0.f; cr[a][b][1] = 0.f; }

    const size_t bblk0 = (size_t)(by * 16 + g * 8) * 16384;   // byte offset of stream's blocks

    // prologue: K=0 of t=0 -> stage 0
    {
        const char* Bx = (const char*)g_xp + bblk0;
        const char* Bh = (const char*)g_hp[0] + bblk0;
        ISSUE_STAGE(0, 0, Bx, Bh); CP_COMMIT();
    }

    for (int t = 0; t < TSTEPS; t++) {
        const char* Bx  = (const char*)g_xp + (size_t)t * 64 * 16384 + bblk0;
        const char* Bh  = (const char*)g_hp[t & 1] + bblk0;
        const char* BxN = Bx + (size_t)64 * 16384;
        __half* hw = g_hp[(t & 1) ^ 1];

        float acc[4][4][4];
#pragma unroll
        for (int a = 0; a < 4; a++)
#pragma unroll
            for (int b = 0; b < 4; b++)
#pragma unroll
                for (int c = 0; c < 4; c++) acc[a][b][c] = 0.f;

        for (int kt = 0; kt < 16; kt++) {
            BARG();                        // all stream warps done computing kt-1
            if (kt == 7 && t > 0) {
                // h needed from K=8 on; every thread spins (no extra barrier)
                const unsigned tgt = (unsigned)t * 32u;
                while (*(volatile unsigned*)&g_sync8[syncIdx] < tgt) { }
                __threadfence();
            }
            const int la = kt + 1;
            if (la < 16) {
                ISSUE_STAGE(la & 1, la, Bx, Bh);
            } else if (t + 1 < TSTEPS) {
                ISSUE_STAGE(0, 0, BxN, Bh);   // next step's K=0 (x-phase)
            }
            CP_COMMIT();
            CP_WAIT1();                    // own copies of K=kt landed
            BARG();                        // everyone's copies of K=kt landed
            COMPUTE_STAGE(kt & 1);
        }

        // ---- fused LSTM epilogue (c in registers) ----
        float hnv[2][4][2];
#pragma unroll
        for (int jhi = 0; jhi < 2; jhi++) {
            const int j = j0 + jhi * 8 + grp;
            const int kt_  = j >> 6;
            const int k16_ = (j >> 4) & 3;
            const int reg_ = (j >> 3) & 1;
            const int tig_ = (j >> 1) & 3;
            const int u_   = j & 1;
            const int jbase = (kt_ * 4 + k16_) * 32;
#pragma unroll
            for (int nj = 0; nj < 4; nj++) {
                const int blk = by * 16 + g * 8 + wn * 4 + nj;
#pragma unroll
                for (int e = 0; e < 2; e++) {
                    const int grp_b = tig * 2 + e;
                    float zi = acc[2 * jhi    ][nj][e]     + bia[jhi][0];
                    float zf = acc[2 * jhi    ][nj][2 + e] + bia[jhi][1];
                    float zg = acc[2 * jhi + 1][nj][e]     + bia[jhi][2];
                    float zo = acc[2 * jhi + 1][nj][2 + e] + bia[jhi][3];

                    float si = sigm_f(zi);
                    float sf = sigm_f(zf);
                    float so = sigm_f(zo);
                    float tg = tanh_f(zg);

                    float cn = sf * cr[jhi][nj][e] + si * tg;
                    float hn = so * tanh_f(cn);
                    cr[jhi][nj][e] = cn;
                    hnv[jhi][nj][e] = hn;
                    hw[(size_t)blk * 8192 + (jbase + grp_b * 4 + tig_) * 4 + reg_ * 2 + u_] =
                        __float2half_rn(hn);
                }
            }
        }

        // publish h for this stream, arrive, then out stores (off critical path)
        BARG();
        if (tid2 == 0) {
            __threadfence();
            atomicAdd(&g_sync8[syncIdx], 1u);
        }

#pragma unroll
        for (int jhi = 0; jhi < 2; jhi++) {
            const int j = j0 + jhi * 8 + grp;
#pragma unroll
            for (int nj = 0; nj < 4; nj++) {
                const int blk = by * 16 + g * 8 + wn * 4 + nj;
#pragma unroll
                for (int e = 0; e < 2; e++) {
                    const int b = blk * 8 + tig * 2 + e;
                    out[(size_t)b * (TSTEPS * HIDDEN) + (size_t)t * 1024 + j] = hnv[jhi][nj][e];
                }
            }
        }
    }
}

// ------------------------------ launch ----------------------------------------
extern "C" void kernel_launch(void* const* d_in, const int* in_sizes, int n_in,
                              void* d_out, int out_size)
{
    const float* x    = (const float*)d_in[0];  // [512, 103, 1024]
    const float* W    = (const float*)d_in[1];  // [1024, 4096]
    const float* R    = (const float*)d_in[2];  // [1024, 4096]
    const float* bias = (const float*)d_in[3];  // [4096]
    float* out = (float*)d_out;                 // [512, 100, 1024]

    cudaFuncSetAttribute(lstm_persist, cudaFuncAttributeMaxDynamicSharedMemorySize, SMEM_SZ);

    const int total = N1 + N2 + N3 + 8;
    prep_all<<<(total + 255) / 256, 256>>>(W, R, x);

    dim3 grid(32, 4);   // 128 CTAs, 1/SM, co-resident
    lstm_persist<<<grid, 256, SMEM_SZ>>>(bias, out);
}